// round 8
// baseline (speedup 1.0000x reference)
#include <cuda_runtime.h>
#include <cuda_bf16.h>
#include <math.h>

#define NN 50000
#define EE 800000
#define FF 128
#define CC 16

// ---------------- scratch (device globals; no allocation allowed) -----------
__device__ float g_deg[NN];
__device__ float g_dinv[NN];
__device__ float g_Z[(size_t)NN * FF];   // GEMM output z = (h@W)*dinv  (also head temp)
__device__ float g_S[(size_t)NN * FF];   // edge-scatter accumulator
__device__ float g_H[(size_t)NN * FF];   // layer activations
__device__ int   g_is64;                 // edge_index dtype flag

// ---------------- helpers ---------------------------------------------------
__device__ __forceinline__ float gelu_exact(float x) {
    return 0.5f * x * (1.0f + erff(x * 0.70710678118654752f));
}

__device__ __forceinline__ int load_idx(const void* p, long long i, int is64) {
    if (is64) return (int)((const long long*)p)[i];
    return ((const int*)p)[i];
}

// ---------------- dtype detection (int64 vs int32 edge_index) ---------------
__global__ void detect_kernel(const unsigned* __restrict__ e) {
    // if int64 little-endian, every odd 32-bit word is a zero high-word
    int is64 = 1;
    for (int i = 0; i < 64; i++) {
        if (e[2 * i + 1] != 0u) { is64 = 0; break; }
    }
    g_is64 = is64;
}

// ---------------- init: S = 0, deg = 1 (self loops) -------------------------
__global__ void init_kernel(float* __restrict__ S) {
    size_t i = (size_t)blockIdx.x * blockDim.x + threadIdx.x;
    if (i < (size_t)NN * (FF / 4))
        ((float4*)S)[i] = make_float4(0.f, 0.f, 0.f, 0.f);
    if (i < NN) g_deg[i] = 1.0f;
}

__global__ void deg_acc_kernel(const void* __restrict__ edges) {
    int e = blockIdx.x * blockDim.x + threadIdx.x;
    if (e >= EE) return;
    int is64 = g_is64;
    int c = load_idx(edges, (long long)EE + e, is64);  // col = edge_index[1]
    atomicAdd(&g_deg[c], 1.0f);
}

__global__ void dinv_kernel() {
    int i = blockIdx.x * blockDim.x + threadIdx.x;
    if (i < NN) g_dinv[i] = rsqrtf(g_deg[i]);
}

// ---------------- conv GEMM: Z = (pre(A) @ W) * dinv[row] -------------------
// A: [NN,128] row-major, W: [128,128] row-major (k-major rows)
// Block: 256 threads, 64 rows. Dynamic smem = W(64KB) + Atile(32KB) = 96KB.
__global__ void __launch_bounds__(256, 2) conv_gemm_kernel(
    const float* __restrict__ A, const float* __restrict__ W,
    const float* __restrict__ imp,  // nullptr for no pre-op
    float* __restrict__ Z)
{
    extern __shared__ float sm[];
    float* Ws = sm;               // 128*128
    float* As = sm + 128 * 128;   // 64*128
    const int tid = threadIdx.x;
    const int rb  = blockIdx.x * 64;

    // load W (16384 floats)
    for (int i = tid; i < 128 * 128 / 4; i += 256)
        ((float4*)Ws)[i] = ((const float4*)W)[i];

    // load A tile with optional importance pre-scale
    for (int i = tid; i < 64 * 32; i += 256) {
        int r = i >> 5, c4 = i & 31;
        int gr = rb + r;
        float4 v = make_float4(0.f, 0.f, 0.f, 0.f);
        if (gr < NN) v = ((const float4*)(A + (size_t)gr * FF))[c4];
        if (imp) {
            float4 iv = ((const float4*)imp)[c4];
            v.x *= iv.x; v.y *= iv.y; v.z *= iv.z; v.w *= iv.w;
        }
        ((float4*)As)[i] = v;
    }
    __syncthreads();

    const int tx = tid & 31;   // column group: cols 4*tx .. 4*tx+3
    const int ty = tid >> 5;   // row group: rows ty*8 .. ty*8+7
    float acc[8][4];
    #pragma unroll
    for (int r = 0; r < 8; r++) { acc[r][0]=acc[r][1]=acc[r][2]=acc[r][3]=0.f; }

    #pragma unroll 4
    for (int k = 0; k < 128; k++) {
        float4 w4 = ((const float4*)(Ws + k * 128))[tx];
        #pragma unroll
        for (int r = 0; r < 8; r++) {
            float a = As[(ty * 8 + r) * 128 + k];   // warp-broadcast
            acc[r][0] += a * w4.x;
            acc[r][1] += a * w4.y;
            acc[r][2] += a * w4.z;
            acc[r][3] += a * w4.w;
        }
    }

    #pragma unroll
    for (int r = 0; r < 8; r++) {
        int gr = rb + ty * 8 + r;
        if (gr < NN) {
            float d = g_dinv[gr];
            float4 o = make_float4(acc[r][0]*d, acc[r][1]*d, acc[r][2]*d, acc[r][3]*d);
            ((float4*)(Z + (size_t)gr * FF))[tx] = o;
        }
    }
}

// ---------------- dense GEMM: T = gelu(A @ W + b) ---------------------------
__global__ void __launch_bounds__(256, 2) dense_gemm_kernel(
    const float* __restrict__ A, const float* __restrict__ W,
    const float* __restrict__ b, float* __restrict__ T)
{
    extern __shared__ float sm[];
    float* Ws = sm;
    float* As = sm + 128 * 128;
    const int tid = threadIdx.x;
    const int rb  = blockIdx.x * 64;

    for (int i = tid; i < 128 * 128 / 4; i += 256)
        ((float4*)Ws)[i] = ((const float4*)W)[i];
    for (int i = tid; i < 64 * 32; i += 256) {
        int r = i >> 5, c4 = i & 31;
        int gr = rb + r;
        float4 v = make_float4(0.f, 0.f, 0.f, 0.f);
        if (gr < NN) v = ((const float4*)(A + (size_t)gr * FF))[c4];
        ((float4*)As)[i] = v;
    }
    __syncthreads();

    const int tx = tid & 31;
    const int ty = tid >> 5;
    float acc[8][4];
    #pragma unroll
    for (int r = 0; r < 8; r++) { acc[r][0]=acc[r][1]=acc[r][2]=acc[r][3]=0.f; }

    #pragma unroll 4
    for (int k = 0; k < 128; k++) {
        float4 w4 = ((const float4*)(Ws + k * 128))[tx];
        #pragma unroll
        for (int r = 0; r < 8; r++) {
            float a = As[(ty * 8 + r) * 128 + k];
            acc[r][0] += a * w4.x;
            acc[r][1] += a * w4.y;
            acc[r][2] += a * w4.z;
            acc[r][3] += a * w4.w;
        }
    }

    float4 bb = ((const float4*)b)[tx];
    #pragma unroll
    for (int r = 0; r < 8; r++) {
        int gr = rb + ty * 8 + r;
        if (gr < NN) {
            float4 o;
            o.x = gelu_exact(acc[r][0] + bb.x);
            o.y = gelu_exact(acc[r][1] + bb.y);
            o.z = gelu_exact(acc[r][2] + bb.z);
            o.w = gelu_exact(acc[r][3] + bb.w);
            ((float4*)(T + (size_t)gr * FF))[tx] = o;
        }
    }
}

// ---------------- edge scatter: S[col] += Z[row] (vector red) ---------------
// one edge per warp: 32 lanes x float4 = full 128-float row
__global__ void __launch_bounds__(256) scatter_kernel(
    const void* __restrict__ edges,
    const float* __restrict__ Z, float* __restrict__ S)
{
    int e = blockIdx.x * 8 + (threadIdx.x >> 5);
    if (e >= EE) return;
    const int lane = threadIdx.x & 31;
    const int is64 = g_is64;
    int r = load_idx(edges, e, is64);                  // row = edge_index[0]
    int c = load_idx(edges, (long long)EE + e, is64);  // col = edge_index[1]

    float4 v = ((const float4*)(Z + (size_t)r * FF))[lane];
    float* dst = S + (size_t)c * FF + lane * 4;
    asm volatile("red.global.add.v4.f32 [%0], {%1, %2, %3, %4};"
                 :: "l"(dst), "f"(v.x), "f"(v.y), "f"(v.z), "f"(v.w)
                 : "memory");
}

// ---------------- post: H = gelu(dinv*(S+Z)+b); S = 0 -----------------------
__global__ void post_kernel(const float* __restrict__ Z, float* __restrict__ S,
                            const float* __restrict__ b, float* __restrict__ Hout)
{
    size_t i = (size_t)blockIdx.x * blockDim.x + threadIdx.x;  // float4 index
    if (i >= (size_t)NN * (FF / 4)) return;
    int node = (int)(i >> 5);
    int c4   = (int)(i & 31);
    float d  = g_dinv[node];
    float4 s = ((const float4*)S)[i];
    float4 z = ((const float4*)Z)[i];
    float4 bb = ((const float4*)b)[c4];
    float4 h;
    h.x = gelu_exact(d * (s.x + z.x) + bb.x);
    h.y = gelu_exact(d * (s.y + z.y) + bb.y);
    h.z = gelu_exact(d * (s.z + z.z) + bb.z);
    h.w = gelu_exact(d * (s.w + z.w) + bb.w);
    ((float4*)Hout)[i] = h;
    ((float4*)S)[i] = make_float4(0.f, 0.f, 0.f, 0.f);  // ready for next layer
}

// ---------------- head GEMM: out = T @ lw2 + lb2  (128 -> 16) ---------------
__global__ void __launch_bounds__(256) head_gemm_kernel(
    const float* __restrict__ T, const float* __restrict__ lw2,
    const float* __restrict__ lb2, float* __restrict__ out)
{
    __shared__ float Ws[128 * 16];     // 8 KB
    __shared__ float As[64 * 132];     // padded to kill bank conflicts (~33 KB)
    const int tid = threadIdx.x;
    const int rb  = blockIdx.x * 64;

    for (int i = tid; i < 128 * 16 / 4; i += 256)
        ((float4*)Ws)[i] = ((const float4*)lw2)[i];
    for (int i = tid; i < 64 * 32; i += 256) {
        int r = i >> 5, c4 = i & 31;
        int gr = rb + r;
        float4 v = make_float4(0.f, 0.f, 0.f, 0.f);
        if (gr < NN) v = ((const float4*)(T + (size_t)gr * FF))[c4];
        *((float4*)(As + r * 132 + c4 * 4)) = v;
    }
    __syncthreads();

    const int row = tid >> 2;   // 64 rows
    const int cg  = tid & 3;    // 4 col-groups of 4
    float acc[4] = {0.f, 0.f, 0.f, 0.f};
    #pragma unroll 8
    for (int k = 0; k < 128; k++) {
        float a = As[row * 132 + k];
        float4 w4 = ((const float4*)(Ws + k * 16))[cg];
        acc[0] += a * w4.x; acc[1] += a * w4.y;
        acc[2] += a * w4.z; acc[3] += a * w4.w;
    }
    int gr = rb + row;
    if (gr < NN) {
        float4 bb = ((const float4*)lb2)[cg];
        float4 o = make_float4(acc[0]+bb.x, acc[1]+bb.y, acc[2]+bb.z, acc[3]+bb.w);
        ((float4*)(out + (size_t)gr * CC))[cg] = o;
    }
}

// ---------------- launch -----------------------------------------------------
extern "C" void kernel_launch(void* const* d_in, const int* in_sizes, int n_in,
                              void* d_out, int out_size)
{
    const float* x   = (const float*)d_in[0];
    const void*  edg = d_in[1];
    const float* imp = (const float*)d_in[2];
    const float* W1  = (const float*)d_in[3];
    const float* b1  = (const float*)d_in[4];
    const float* W2  = (const float*)d_in[5];
    const float* b2  = (const float*)d_in[6];
    const float* W3  = (const float*)d_in[7];
    const float* b3  = (const float*)d_in[8];
    const float* lw1 = (const float*)d_in[9];
    const float* lb1 = (const float*)d_in[10];
    const float* lw2 = (const float*)d_in[11];
    const float* lb2 = (const float*)d_in[12];
    float* out = (float*)d_out;

    float *Z, *S, *H;
    cudaGetSymbolAddress((void**)&Z, g_Z);
    cudaGetSymbolAddress((void**)&S, g_S);
    cudaGetSymbolAddress((void**)&H, g_H);

    const int SMEM = 96 * 1024;
    cudaFuncSetAttribute(conv_gemm_kernel,  cudaFuncAttributeMaxDynamicSharedMemorySize, SMEM);
    cudaFuncSetAttribute(dense_gemm_kernel, cudaFuncAttributeMaxDynamicSharedMemorySize, SMEM);

    const int GB   = (NN + 63) / 64;                 // 782 GEMM blocks
    const int EW   = EE / 8;                         // 100000 scatter blocks (8 edges/block)
    const int ELEM = ((NN * (FF / 4)) + 255) / 256;  // 6250 elementwise blocks

    detect_kernel<<<1, 1>>>((const unsigned*)edg);
    init_kernel<<<ELEM, 256>>>(S);                   // S = 0, deg = 1
    deg_acc_kernel<<<(EE + 255) / 256, 256>>>(edg);
    dinv_kernel<<<(NN + 255) / 256, 256>>>();

    // layer 1 (pre-op: importance)
    conv_gemm_kernel<<<GB, 256, SMEM>>>(x, W1, imp, Z);
    scatter_kernel<<<EW, 256>>>(edg, Z, S);
    post_kernel<<<ELEM, 256>>>(Z, S, b1, H);

    // layer 2
    conv_gemm_kernel<<<GB, 256, SMEM>>>(H, W2, nullptr, Z);
    scatter_kernel<<<EW, 256>>>(edg, Z, S);
    post_kernel<<<ELEM, 256>>>(Z, S, b2, H);

    // layer 3
    conv_gemm_kernel<<<GB, 256, SMEM>>>(H, W3, nullptr, Z);
    scatter_kernel<<<EW, 256>>>(edg, Z, S);
    post_kernel<<<ELEM, 256>>>(Z, S, b3, H);

    // head: T = gelu(H@lw1 + lb1)  (reuse Z as T), then out = T@lw2 + lb2
    dense_gemm_kernel<<<GB, 256, SMEM>>>(H, lw1, lb1, Z);
    head_gemm_kernel<<<GB, 256>>>(Z, lw2, lb2, out);
}

// round 9
// speedup vs baseline: 1.3010x; 1.3010x over previous
#include <cuda_runtime.h>
#include <cuda_bf16.h>
#include <math.h>

#define NN 50000
#define EE 800000
#define FF 128
#define CC 16
#define SCAN_B 1024

// ---------------- scratch (device globals; no allocation allowed) -----------
__device__ int   g_cnt[NN];        // in-degree (excl. self loop)
__device__ int   g_cursor[NN];     // fill cursors
__device__ int   g_rowstart[NN + 1];
__device__ int   g_srows[EE];      // edge source rows, bucketed by dest
__device__ float g_dinv[NN];
__device__ float g_Z[(size_t)NN * FF];   // GEMM output z = (h@W)*dinv (also head temp)
__device__ float g_H[(size_t)NN * FF];   // layer activations
__device__ int   g_is64;                 // edge_index dtype flag

// ---------------- helpers ---------------------------------------------------
__device__ __forceinline__ float gelu_exact(float x) {
    return 0.5f * x * (1.0f + erff(x * 0.70710678118654752f));
}

__device__ __forceinline__ int load_idx(const void* p, long long i, int is64) {
    if (is64) return (int)((const long long*)p)[i];
    return ((const int*)p)[i];
}

// ---------------- dtype detection (int64 vs int32 edge_index) ---------------
__global__ void detect_kernel(const unsigned* __restrict__ e) {
    int is64 = 1;
    for (int i = 0; i < 64; i++) {
        if (e[2 * i + 1] != 0u) { is64 = 0; break; }
    }
    g_is64 = is64;
}

// ---------------- CSR build --------------------------------------------------
__global__ void zero_cnt_kernel() {
    int i = blockIdx.x * blockDim.x + threadIdx.x;
    if (i < NN) { g_cnt[i] = 0; g_cursor[i] = 0; }
}

__global__ void hist_kernel(const void* __restrict__ edges) {
    int e = blockIdx.x * blockDim.x + threadIdx.x;
    if (e >= EE) return;
    int c = load_idx(edges, (long long)EE + e, g_is64);  // col = edge_index[1]
    atomicAdd(&g_cnt[c], 1);
}

__global__ void dinv_kernel() {
    int i = blockIdx.x * blockDim.x + threadIdx.x;
    if (i < NN) g_dinv[i] = rsqrtf((float)(g_cnt[i] + 1));  // + self loop
}

// single-block sequential-chunk exclusive scan of g_cnt -> g_rowstart
__global__ void scan_kernel() {
    __shared__ int s[SCAN_B];
    __shared__ int carry_s;
    const int tid = threadIdx.x;
    if (tid == 0) carry_s = 0;
    __syncthreads();
    for (int base = 0; base < NN; base += SCAN_B) {
        int i = base + tid;
        int v = (i < NN) ? g_cnt[i] : 0;
        s[tid] = v;
        __syncthreads();
        #pragma unroll
        for (int off = 1; off < SCAN_B; off <<= 1) {
            int t = (tid >= off) ? s[tid - off] : 0;
            __syncthreads();
            s[tid] += t;
            __syncthreads();
        }
        int incl  = s[tid];
        int carry = carry_s;
        if (i < NN) g_rowstart[i] = carry + incl - v;   // exclusive
        __syncthreads();
        if (tid == SCAN_B - 1) carry_s = carry + incl;
        __syncthreads();
    }
    if (tid == 0) g_rowstart[NN] = carry_s;
}

__global__ void fill_kernel(const void* __restrict__ edges) {
    int e = blockIdx.x * blockDim.x + threadIdx.x;
    if (e >= EE) return;
    int is64 = g_is64;
    int r = load_idx(edges, e, is64);                    // row = edge_index[0]
    int c = load_idx(edges, (long long)EE + e, is64);    // col
    int p = g_rowstart[c] + atomicAdd(&g_cursor[c], 1);
    g_srows[p] = r;
}

// ---------------- conv GEMM: Z = (pre(A) @ W) * dinv[row] -------------------
__global__ void __launch_bounds__(256, 2) conv_gemm_kernel(
    const float* __restrict__ A, const float* __restrict__ W,
    const float* __restrict__ imp,  // nullptr for no pre-op
    float* __restrict__ Z)
{
    extern __shared__ float sm[];
    float* Ws = sm;               // 128*128
    float* As = sm + 128 * 128;   // 64*128
    const int tid = threadIdx.x;
    const int rb  = blockIdx.x * 64;

    for (int i = tid; i < 128 * 128 / 4; i += 256)
        ((float4*)Ws)[i] = ((const float4*)W)[i];

    for (int i = tid; i < 64 * 32; i += 256) {
        int r = i >> 5, c4 = i & 31;
        int gr = rb + r;
        float4 v = make_float4(0.f, 0.f, 0.f, 0.f);
        if (gr < NN) v = ((const float4*)(A + (size_t)gr * FF))[c4];
        if (imp) {
            float4 iv = ((const float4*)imp)[c4];
            v.x *= iv.x; v.y *= iv.y; v.z *= iv.z; v.w *= iv.w;
        }
        ((float4*)As)[i] = v;
    }
    __syncthreads();

    const int tx = tid & 31;
    const int ty = tid >> 5;
    float acc[8][4];
    #pragma unroll
    for (int r = 0; r < 8; r++) { acc[r][0]=acc[r][1]=acc[r][2]=acc[r][3]=0.f; }

    #pragma unroll 4
    for (int k = 0; k < 128; k++) {
        float4 w4 = ((const float4*)(Ws + k * 128))[tx];
        #pragma unroll
        for (int r = 0; r < 8; r++) {
            float a = As[(ty * 8 + r) * 128 + k];
            acc[r][0] += a * w4.x;
            acc[r][1] += a * w4.y;
            acc[r][2] += a * w4.z;
            acc[r][3] += a * w4.w;
        }
    }

    #pragma unroll
    for (int r = 0; r < 8; r++) {
        int gr = rb + ty * 8 + r;
        if (gr < NN) {
            float d = g_dinv[gr];
            float4 o = make_float4(acc[r][0]*d, acc[r][1]*d, acc[r][2]*d, acc[r][3]*d);
            ((float4*)(Z + (size_t)gr * FF))[tx] = o;
        }
    }
}

// ---------------- dense GEMM: T = gelu(A @ W + b) ---------------------------
__global__ void __launch_bounds__(256, 2) dense_gemm_kernel(
    const float* __restrict__ A, const float* __restrict__ W,
    const float* __restrict__ b, float* __restrict__ T)
{
    extern __shared__ float sm[];
    float* Ws = sm;
    float* As = sm + 128 * 128;
    const int tid = threadIdx.x;
    const int rb  = blockIdx.x * 64;

    for (int i = tid; i < 128 * 128 / 4; i += 256)
        ((float4*)Ws)[i] = ((const float4*)W)[i];
    for (int i = tid; i < 64 * 32; i += 256) {
        int r = i >> 5, c4 = i & 31;
        int gr = rb + r;
        float4 v = make_float4(0.f, 0.f, 0.f, 0.f);
        if (gr < NN) v = ((const float4*)(A + (size_t)gr * FF))[c4];
        ((float4*)As)[i] = v;
    }
    __syncthreads();

    const int tx = tid & 31;
    const int ty = tid >> 5;
    float acc[8][4];
    #pragma unroll
    for (int r = 0; r < 8; r++) { acc[r][0]=acc[r][1]=acc[r][2]=acc[r][3]=0.f; }

    #pragma unroll 4
    for (int k = 0; k < 128; k++) {
        float4 w4 = ((const float4*)(Ws + k * 128))[tx];
        #pragma unroll
        for (int r = 0; r < 8; r++) {
            float a = As[(ty * 8 + r) * 128 + k];
            acc[r][0] += a * w4.x;
            acc[r][1] += a * w4.y;
            acc[r][2] += a * w4.z;
            acc[r][3] += a * w4.w;
        }
    }

    float4 bb = ((const float4*)b)[tx];
    #pragma unroll
    for (int r = 0; r < 8; r++) {
        int gr = rb + ty * 8 + r;
        if (gr < NN) {
            float4 o;
            o.x = gelu_exact(acc[r][0] + bb.x);
            o.y = gelu_exact(acc[r][1] + bb.y);
            o.z = gelu_exact(acc[r][2] + bb.z);
            o.w = gelu_exact(acc[r][3] + bb.w);
            ((float4*)(T + (size_t)gr * FF))[tx] = o;
        }
    }
}

// ---------------- fused gather: H[c] = gelu(dinv[c]*(Z[c] + sum Z[srcs]) + b)
// one warp per destination node; 4 floats per lane; no atomics.
__global__ void __launch_bounds__(256) gather_kernel(
    const float* __restrict__ Z, const float* __restrict__ b,
    float* __restrict__ Hout)
{
    int node = blockIdx.x * 8 + (threadIdx.x >> 5);
    if (node >= NN) return;
    const int lane = threadIdx.x & 31;

    float4 acc = ((const float4*)(Z + (size_t)node * FF))[lane];  // self loop
    const int start = g_rowstart[node];
    const int n     = g_cnt[node];

    for (int base = 0; base < n; base += 32) {
        int m = n - base; if (m > 32) m = 32;
        int idx = (lane < m) ? g_srows[start + base + lane] : 0;
        for (int j = 0; j < m; j++) {
            int r = __shfl_sync(0xffffffffu, idx, j);
            float4 v = ((const float4*)(Z + (size_t)r * FF))[lane];
            acc.x += v.x; acc.y += v.y; acc.z += v.z; acc.w += v.w;
        }
    }

    float d = g_dinv[node];
    float4 bb = ((const float4*)b)[lane];
    float4 h;
    h.x = gelu_exact(d * acc.x + bb.x);
    h.y = gelu_exact(d * acc.y + bb.y);
    h.z = gelu_exact(d * acc.z + bb.z);
    h.w = gelu_exact(d * acc.w + bb.w);
    ((float4*)(Hout + (size_t)node * FF))[lane] = h;
}

// ---------------- head GEMM: out = T @ lw2 + lb2  (128 -> 16) ---------------
__global__ void __launch_bounds__(256) head_gemm_kernel(
    const float* __restrict__ T, const float* __restrict__ lw2,
    const float* __restrict__ lb2, float* __restrict__ out)
{
    __shared__ float Ws[128 * 16];
    __shared__ float As[64 * 132];
    const int tid = threadIdx.x;
    const int rb  = blockIdx.x * 64;

    for (int i = tid; i < 128 * 16 / 4; i += 256)
        ((float4*)Ws)[i] = ((const float4*)lw2)[i];
    for (int i = tid; i < 64 * 32; i += 256) {
        int r = i >> 5, c4 = i & 31;
        int gr = rb + r;
        float4 v = make_float4(0.f, 0.f, 0.f, 0.f);
        if (gr < NN) v = ((const float4*)(T + (size_t)gr * FF))[c4];
        *((float4*)(As + r * 132 + c4 * 4)) = v;
    }
    __syncthreads();

    const int row = tid >> 2;
    const int cg  = tid & 3;
    float acc[4] = {0.f, 0.f, 0.f, 0.f};
    #pragma unroll 8
    for (int k = 0; k < 128; k++) {
        float a = As[row * 132 + k];
        float4 w4 = ((const float4*)(Ws + k * 16))[cg];
        acc[0] += a * w4.x; acc[1] += a * w4.y;
        acc[2] += a * w4.z; acc[3] += a * w4.w;
    }
    int gr = rb + row;
    if (gr < NN) {
        float4 bb = ((const float4*)lb2)[cg];
        float4 o = make_float4(acc[0]+bb.x, acc[1]+bb.y, acc[2]+bb.z, acc[3]+bb.w);
        ((float4*)(out + (size_t)gr * CC))[cg] = o;
    }
}

// ---------------- launch -----------------------------------------------------
extern "C" void kernel_launch(void* const* d_in, const int* in_sizes, int n_in,
                              void* d_out, int out_size)
{
    const float* x   = (const float*)d_in[0];
    const void*  edg = d_in[1];
    const float* imp = (const float*)d_in[2];
    const float* W1  = (const float*)d_in[3];
    const float* b1  = (const float*)d_in[4];
    const float* W2  = (const float*)d_in[5];
    const float* b2  = (const float*)d_in[6];
    const float* W3  = (const float*)d_in[7];
    const float* b3  = (const float*)d_in[8];
    const float* lw1 = (const float*)d_in[9];
    const float* lb1 = (const float*)d_in[10];
    const float* lw2 = (const float*)d_in[11];
    const float* lb2 = (const float*)d_in[12];
    float* out = (float*)d_out;

    float *Z, *H;
    cudaGetSymbolAddress((void**)&Z, g_Z);
    cudaGetSymbolAddress((void**)&H, g_H);

    const int SMEM = 96 * 1024;
    cudaFuncSetAttribute(conv_gemm_kernel,  cudaFuncAttributeMaxDynamicSharedMemorySize, SMEM);
    cudaFuncSetAttribute(dense_gemm_kernel, cudaFuncAttributeMaxDynamicSharedMemorySize, SMEM);

    const int GB = (NN + 63) / 64;        // 782 GEMM blocks
    const int NW = (NN + 7) / 8;          // 6250 gather blocks (8 nodes/block)
    const int NB = (NN + 255) / 256;      // node-wise blocks
    const int EB = (EE + 255) / 256;      // edge-wise blocks

    // CSR build (graph-capturable; no allocations)
    detect_kernel<<<1, 1>>>((const unsigned*)edg);
    zero_cnt_kernel<<<NB, 256>>>();
    hist_kernel<<<EB, 256>>>(edg);
    dinv_kernel<<<NB, 256>>>();
    scan_kernel<<<1, SCAN_B>>>();
    fill_kernel<<<EB, 256>>>(edg);

    // layer 1 (pre-op: importance)
    conv_gemm_kernel<<<GB, 256, SMEM>>>(x, W1, imp, Z);
    gather_kernel<<<NW, 256>>>(Z, b1, H);

    // layer 2
    conv_gemm_kernel<<<GB, 256, SMEM>>>(H, W2, nullptr, Z);
    gather_kernel<<<NW, 256>>>(Z, b2, H);

    // layer 3
    conv_gemm_kernel<<<GB, 256, SMEM>>>(H, W3, nullptr, Z);
    gather_kernel<<<NW, 256>>>(Z, b3, H);

    // head: T = gelu(H@lw1 + lb1) (reuse Z as T), then out = T@lw2 + lb2
    dense_gemm_kernel<<<GB, 256, SMEM>>>(H, lw1, lb1, Z);
    head_gemm_kernel<<<GB, 256>>>(Z, lw2, lb2, out);
}